// round 5
// baseline (speedup 1.0000x reference)
#include <cuda_runtime.h>
#include <cstdint>
#include <math.h>

#define NUM_C   10
#define OUT_CH  16
#define BATCH   256
#define KDIM    9216
#define NCOL    160

#define KSPLIT  72
#define KPER    128            /* K per split */
#define KT      16             /* K per stage */
#define NSTAGE  8
#define NTHR    256            /* 32 bgroups(8b) x 8 ngroups(10n) */

/* partials: [KSPLIT][b(256)][n(160)] */
__device__ float g_Upart[KSPLIT * BATCH * NCOL];

/* smem per buffer (floats): x[16][264] = 4224, w[16][80] = 1280 -> 5504 */
#define XROW    264
#define XBUF_F  (KT * XROW)
#define WROW    80
#define WBUF_F  (KT * WROW)
#define BUF_F   (XBUF_F + WBUF_F)

__device__ __forceinline__ uint32_t smem_u32(const void* p) {
    uint32_t a;
    asm("{ .reg .u64 t; cvta.to.shared.u64 t, %1; cvt.u32.u64 %0, t; }"
        : "=r"(a) : "l"(p));
    return a;
}
__device__ __forceinline__ void cp4(uint32_t dst, const void* src) {
    asm volatile("cp.async.ca.shared.global [%0], [%1], 4;"
                 :: "r"(dst), "l"(src) : "memory");
}
__device__ __forceinline__ void cp16(uint32_t dst, const void* src) {
    asm volatile("cp.async.cg.shared.global [%0], [%1], 16;"
                 :: "r"(dst), "l"(src) : "memory");
}
__device__ __forceinline__ void cp_commit() {
    asm volatile("cp.async.commit_group;" ::: "memory");
}
__device__ __forceinline__ void cp_wait1() {
    asm volatile("cp.async.wait_group 1;" ::: "memory");
}
__device__ __forceinline__ void cp_wait0() {
    asm volatile("cp.async.wait_group 0;" ::: "memory");
}
__device__ __forceinline__ unsigned long long bcast2(float a) {
    unsigned long long r;
    asm("mov.b64 %0, {%1, %1};" : "=l"(r) : "f"(a));
    return r;
}
__device__ __forceinline__ void fma2(unsigned long long& d,
                                     unsigned long long a,
                                     unsigned long long b) {
    asm("fma.rn.f32x2 %0, %1, %2, %0;" : "+l"(d) : "l"(a), "l"(b));
}
__device__ __forceinline__ float2 unp2(unsigned long long v) {
    float2 r;
    asm("mov.b64 {%0, %1}, %2;" : "=f"(r.x), "=f"(r.y) : "l"(v));
    return r;
}

/* stage: x tile [KT k][256 b] via 4B cp.async (transposing), w tile [KT k][80 n] via 16B */
__device__ __forceinline__ void stage_load(
    const float* __restrict__ x, const float* __restrict__ w,
    int nh, int k0, uint32_t sx, uint32_t sw, int tid)
{
    /* x: 4096 scalars; fid = b*16 + kloc; 16 consecutive lanes read 64B of one b-row */
    #pragma unroll
    for (int j = 0; j < 16; j++) {
        int fid  = j * NTHR + tid;
        int b    = fid >> 4;
        int kloc = fid & 15;
        cp4(sx + (uint32_t)(kloc * XROW + b) * 4,
            x + (size_t)b * KDIM + k0 + kloc);
    }
    /* w: 320 float4; fid = kloc*20 + e; n = nh*80 + e*4 -> (c,o) */
    #pragma unroll
    for (int j = 0; j < 2; j++) {
        int fid = j * NTHR + tid;
        if (fid < 320) {
            int kloc = fid / 20;
            int e    = fid % 20;
            int n    = nh * 80 + e * 4;
            int c    = n >> 4;
            int o    = n & 15;
            cp16(sw + (uint32_t)(kloc * WROW + e * 4) * 4,
                 w + ((size_t)c * KDIM + k0 + kloc) * 16 + o);
        }
    }
}

/* ============ GEMM: U[b,n] = sum_k x[b,k]*W[n,k], FFMA2, split-K ============ */
__global__ void __launch_bounds__(NTHR, 1)
gemm_kernel(const float* __restrict__ x, const float* __restrict__ w) {
    __shared__ __align__(16) float smem[2 * BUF_F];   /* 44032 B, static */

    const int tid = threadIdx.x;
    const int ng  = tid & 7;          /* 10 n's: ng*10..ng*10+9 (within half) */
    const int bg  = tid >> 3;         /* 8 b's: bg*8..bg*8+7 */
    const int ks  = blockIdx.x;
    const int nh  = blockIdx.y;
    const int kbase = ks * KPER;

    const uint32_t sb  = smem_u32(smem);
    const uint32_t sx0 = sb;
    const uint32_t sw0 = sb + XBUF_F * 4;
    const uint32_t sx1 = sb + BUF_F * 4;
    const uint32_t sw1 = sb + (BUF_F + XBUF_F) * 4;

    unsigned long long acc[10][4];
    #pragma unroll
    for (int j = 0; j < 10; j++)
        #pragma unroll
        for (int e = 0; e < 4; e++) acc[j][e] = 0ull;

    stage_load(x, w, nh, kbase, sx0, sw0, tid);
    cp_commit();
    stage_load(x, w, nh, kbase + KT, sx1, sw1, tid);
    cp_commit();

    #pragma unroll
    for (int s = 0; s < NSTAGE; s++) {
        if (s < NSTAGE - 1) cp_wait1(); else cp_wait0();
        __syncthreads();

        const float* xs = smem + (s & 1) * BUF_F;
        const float* ws = smem + (s & 1) * BUF_F + XBUF_F;

        #pragma unroll 4
        for (int kk = 0; kk < KT; kk++) {
            /* x: 8 consecutive b's as 4 f32x2 pairs, 2 LDS.128 (conflict-free) */
            const float* xrow = xs + kk * XROW + bg * 8;
            ulonglong2 p0 = *(const ulonglong2*)xrow;
            ulonglong2 p1 = *(const ulonglong2*)(xrow + 4);
            /* w: 10 scalar broadcasts (distinct banks across ng) */
            const float* wrow = ws + kk * WROW + ng * 10;
            #pragma unroll
            for (int j = 0; j < 10; j++) {
                unsigned long long wb = bcast2(wrow[j]);
                fma2(acc[j][0], wb, p0.x);
                fma2(acc[j][1], wb, p0.y);
                fma2(acc[j][2], wb, p1.x);
                fma2(acc[j][3], wb, p1.y);
            }
        }

        if (s + 2 < NSTAGE) {
            __syncthreads();   /* readers done with buffer (s&1) */
            stage_load(x, w, nh, kbase + (s + 2) * KT,
                       (s & 1) ? sx1 : sx0, (s & 1) ? sw1 : sw0, tid);
            cp_commit();
        }
    }

    /* epilogue: [ks][b][n]; per (b): 5 x STG.64, n-contiguous, 8B aligned */
    const int nbase = nh * 80 + ng * 10;
    #pragma unroll
    for (int e = 0; e < 4; e++) {
        float2 lo[10];
        #pragma unroll
        for (int j = 0; j < 10; j++) lo[j] = unp2(acc[j][e]);
        #pragma unroll
        for (int h = 0; h < 2; h++) {
            const int b = bg * 8 + 2 * e + h;
            float* dst = g_Upart + ((size_t)ks * BATCH + b) * NCOL + nbase;
            #pragma unroll
            for (int j = 0; j < 5; j++) {
                float2 v;
                v.x = h ? lo[2 * j].y     : lo[2 * j].x;
                v.y = h ? lo[2 * j + 1].y : lo[2 * j + 1].x;
                ((float2*)dst)[j] = v;
            }
        }
    }
}

/* ===== fused reduce (72-way) + collapsed dynamic routing ===== */
__global__ void __launch_bounds__(NCOL)
routing_kernel(float* __restrict__ out) {
    const int b   = blockIdx.x;
    const int tid = threadIdx.x;   /* = c*16 + o */
    const int c   = tid >> 4;
    const int o   = tid & 15;

    float a[8] = {0.f, 0.f, 0.f, 0.f, 0.f, 0.f, 0.f, 0.f};
    #pragma unroll
    for (int ks = 0; ks < KSPLIT; ks++)
        a[ks & 7] += g_Upart[((size_t)ks * BATCH + b) * NCOL + tid];
    const float u = ((a[0] + a[1]) + (a[2] + a[3]))
                  + ((a[4] + a[5]) + (a[6] + a[7]));

    __shared__ float L[NUM_C];
    if (tid < NUM_C) L[tid] = 0.f;
    __syncthreads();

    float v = 0.f;
    for (int it = 0; it < 3; it++) {
        float mx = L[0];
        #pragma unroll
        for (int j = 1; j < NUM_C; j++) mx = fmaxf(mx, L[j]);
        float den = 0.f;
        #pragma unroll
        for (int j = 0; j < NUM_C; j++) den += __expf(L[j] - mx);
        float p = __expf(L[c] - mx) / den;

        float t = p * u;
        v = t * fabsf(t) / (1.f + t * t);

        float S = v;
        S += __shfl_xor_sync(0xffffffffu, S, 8);
        S += __shfl_xor_sync(0xffffffffu, S, 4);
        S += __shfl_xor_sync(0xffffffffu, S, 2);
        S += __shfl_xor_sync(0xffffffffu, S, 1);

        __syncthreads();
        if (o == 0) L[c] += p * S;
        __syncthreads();
    }
    out[(size_t)b * NCOL + tid] = v;
}

extern "C" void kernel_launch(void* const* d_in, const int* in_sizes, int n_in,
                              void* d_out, int out_size) {
    const float* x = (const float*)d_in[0];
    const float* w = (const float*)d_in[1];
    if (n_in >= 2 && in_sizes[0] == NUM_C * KDIM * OUT_CH) {
        w = (const float*)d_in[0];
        x = (const float*)d_in[1];
    }
    gemm_kernel<<<dim3(KSPLIT, 2), NTHR>>>(x, w);
    routing_kernel<<<BATCH, NCOL>>>((float*)d_out);
    (void)out_size;
}

// round 6
// speedup vs baseline: 1.5714x; 1.5714x over previous
#include <cuda_runtime.h>
#include <cuda_bf16.h>
#include <mma.h>
#include <cstdint>
#include <math.h>

using namespace nvcuda;

#define NUM_C   10
#define OUT_CH  16
#define BATCH   256
#define KDIM    9216
#define NCOL    160

#define KSPLIT  72
#define KPER    128            /* K per block */
#define KT      16             /* K per stage = one wmma k-step */
#define NSTG    8              /* KPER/KT */
#define NTHR    256
#define LDA     24             /* padded lds (elements), 48B rows: LDSM conflict-free */

/* partials: [KSPLIT][b(256)][n(160)] */
__device__ float g_Upart[KSPLIT * BATCH * NCOL];

__device__ __forceinline__ __nv_bfloat16 bhi(float x) { return __float2bfloat16_rn(x); }

/* ============ GEMM: 3-pass bf16-split wmma, split-K ============ */
__global__ void __launch_bounds__(NTHR, 1)
gemm_kernel(const float* __restrict__ x, const float* __restrict__ w) {
    __shared__ __align__(16) __nv_bfloat16 Ah[256 * LDA];
    __shared__ __align__(16) __nv_bfloat16 Al[256 * LDA];
    __shared__ __align__(16) __nv_bfloat16 Bh[80 * LDA];
    __shared__ __align__(16) __nv_bfloat16 Bl[80 * LDA];

    const int tid  = threadIdx.x;
    const int warp = tid >> 5;
    const int ks   = blockIdx.x;
    const int nh   = blockIdx.y;
    const int kbase = ks * KPER;

    const float4* __restrict__ x4 = (const float4*)x;
    const float4* __restrict__ w4 = (const float4*)w;

    wmma::fragment<wmma::accumulator, 16, 16, 16, float> c[2][5];
    #pragma unroll
    for (int mt = 0; mt < 2; mt++)
        #pragma unroll
        for (int nt = 0; nt < 5; nt++) wmma::fill_fragment(c[mt][nt], 0.0f);

    /* prefetch registers */
    float4 rx[4], rw0, rw1;
    const int xb = tid >> 2;        /* + j*64 */
    const int xq = tid & 3;

    /* load stage 0 */
    {
        const int k0 = kbase;
        #pragma unroll
        for (int j = 0; j < 4; j++)
            rx[j] = x4[(size_t)(j * 64 + xb) * (KDIM / 4) + ((k0 + xq * 4) >> 2)];
        {
            int fid = tid, c_loc = fid >> 6, rem = fid & 63;
            rw0 = w4[(size_t)((nh * 5 + c_loc) * KDIM + k0 + (rem >> 2)) * 4 + (rem & 3)];
        }
        if (tid < 64) {
            int fid = 256 + tid, c_loc = fid >> 6, rem = fid & 63;
            rw1 = w4[(size_t)((nh * 5 + c_loc) * KDIM + k0 + (rem >> 2)) * 4 + (rem & 3)];
        }
    }

    #pragma unroll
    for (int s = 0; s < NSTG; s++) {
        __syncthreads();   /* previous stage's readers done */

        /* convert + store x tile */
        #pragma unroll
        for (int j = 0; j < 4; j++) {
            float4 v = rx[j];
            float f[4] = {v.x, v.y, v.z, v.w};
            __nv_bfloat16 h[4], l[4];
            #pragma unroll
            for (int e = 0; e < 4; e++) {
                h[e] = bhi(f[e]);
                l[e] = bhi(f[e] - __bfloat162float(h[e]));
            }
            int b = j * 64 + xb;
            __nv_bfloat162* ph = (__nv_bfloat162*)&Ah[b * LDA + xq * 4];
            __nv_bfloat162* pl = (__nv_bfloat162*)&Al[b * LDA + xq * 4];
            ph[0] = __halves2bfloat162(h[0], h[1]);
            ph[1] = __halves2bfloat162(h[2], h[3]);
            pl[0] = __halves2bfloat162(l[0], l[1]);
            pl[1] = __halves2bfloat162(l[2], l[3]);
        }
        /* convert + store w tile */
        {
            int fid = tid, c_loc = fid >> 6, rem = fid & 63;
            int kloc = rem >> 2, o4 = rem & 3;
            float f[4] = {rw0.x, rw0.y, rw0.z, rw0.w};
            #pragma unroll
            for (int e = 0; e < 4; e++) {
                int n_loc = c_loc * 16 + o4 * 4 + e;
                __nv_bfloat16 h = bhi(f[e]);
                Bh[n_loc * LDA + kloc] = h;
                Bl[n_loc * LDA + kloc] = bhi(f[e] - __bfloat162float(h));
            }
        }
        if (tid < 64) {
            int fid = 256 + tid, c_loc = fid >> 6, rem = fid & 63;
            int kloc = rem >> 2, o4 = rem & 3;
            float f[4] = {rw1.x, rw1.y, rw1.z, rw1.w};
            #pragma unroll
            for (int e = 0; e < 4; e++) {
                int n_loc = c_loc * 16 + o4 * 4 + e;
                __nv_bfloat16 h = bhi(f[e]);
                Bh[n_loc * LDA + kloc] = h;
                Bl[n_loc * LDA + kloc] = bhi(f[e] - __bfloat162float(h));
            }
        }
        __syncthreads();

        /* issue next-stage global loads (overlap with MMA) */
        if (s + 1 < NSTG) {
            const int k0 = kbase + (s + 1) * KT;
            #pragma unroll
            for (int j = 0; j < 4; j++)
                rx[j] = x4[(size_t)(j * 64 + xb) * (KDIM / 4) + ((k0 + xq * 4) >> 2)];
            {
                int fid = tid, c_loc = fid >> 6, rem = fid & 63;
                rw0 = w4[(size_t)((nh * 5 + c_loc) * KDIM + k0 + (rem >> 2)) * 4 + (rem & 3)];
            }
            if (tid < 64) {
                int fid = 256 + tid, c_loc = fid >> 6, rem = fid & 63;
                rw1 = w4[(size_t)((nh * 5 + c_loc) * KDIM + k0 + (rem >> 2)) * 4 + (rem & 3)];
            }
        }

        /* compute: warp -> m rows [warp*32, +32) */
        {
            const int m0 = warp * 32;
            wmma::fragment<wmma::matrix_a, 16, 16, 16, __nv_bfloat16, wmma::row_major> ah0, ah1, al0, al1;
            wmma::load_matrix_sync(ah0, &Ah[m0 * LDA], LDA);
            wmma::load_matrix_sync(ah1, &Ah[(m0 + 16) * LDA], LDA);
            wmma::load_matrix_sync(al0, &Al[m0 * LDA], LDA);
            wmma::load_matrix_sync(al1, &Al[(m0 + 16) * LDA], LDA);
            #pragma unroll
            for (int nt = 0; nt < 5; nt++) {
                wmma::fragment<wmma::matrix_b, 16, 16, 16, __nv_bfloat16, wmma::col_major> bh, bl;
                wmma::load_matrix_sync(bh, &Bh[nt * 16 * LDA], LDA);
                wmma::load_matrix_sync(bl, &Bl[nt * 16 * LDA], LDA);
                wmma::mma_sync(c[0][nt], ah0, bh, c[0][nt]);
                wmma::mma_sync(c[1][nt], ah1, bh, c[1][nt]);
                wmma::mma_sync(c[0][nt], ah0, bl, c[0][nt]);
                wmma::mma_sync(c[1][nt], ah1, bl, c[1][nt]);
                wmma::mma_sync(c[0][nt], al0, bh, c[0][nt]);
                wmma::mma_sync(c[1][nt], al1, bh, c[1][nt]);
            }
        }
    }

    /* epilogue: partials [ks][b][n] */
    {
        const int m0 = warp * 32;
        float* base = g_Upart + (size_t)ks * BATCH * NCOL;
        #pragma unroll
        for (int mt = 0; mt < 2; mt++)
            #pragma unroll
            for (int nt = 0; nt < 5; nt++)
                wmma::store_matrix_sync(
                    base + (size_t)(m0 + mt * 16) * NCOL + nh * 80 + nt * 16,
                    c[mt][nt], NCOL, wmma::mem_row_major);
    }
}

/* ===== fused 72-way reduce (4-way parallel) + collapsed routing ===== */
__global__ void __launch_bounds__(640)
routing_kernel(float* __restrict__ out) {
    const int b   = blockIdx.x;
    const int t   = threadIdx.x;       /* 0..639 */
    const int col = t % NCOL;
    const int prt = t / NCOL;          /* 0..3 */

    float s = 0.f;
    #pragma unroll
    for (int i = 0; i < 18; i++)
        s += g_Upart[((size_t)(prt * 18 + i) * BATCH + b) * NCOL + col];

    __shared__ float red[4][NCOL];
    __shared__ float L[NUM_C];
    red[prt][col] = s;
    if (t < NUM_C) L[t] = 0.f;
    __syncthreads();

    const int c = col >> 4;
    const int o = col & 15;
    float u = 0.f, v = 0.f;
    if (t < NCOL)
        u = (red[0][col] + red[1][col]) + (red[2][col] + red[3][col]);

    for (int it = 0; it < 3; it++) {
        float p = 0.f, S = 0.f;
        if (t < NCOL) {
            float mx = L[0];
            #pragma unroll
            for (int j = 1; j < NUM_C; j++) mx = fmaxf(mx, L[j]);
            float den = 0.f;
            #pragma unroll
            for (int j = 0; j < NUM_C; j++) den += __expf(L[j] - mx);
            p = __expf(L[c] - mx) / den;

            float tt = p * u;
            v = tt * fabsf(tt) / (1.f + tt * tt);

            S = v;
            S += __shfl_xor_sync(0xffffffffu, S, 8);
            S += __shfl_xor_sync(0xffffffffu, S, 4);
            S += __shfl_xor_sync(0xffffffffu, S, 2);
            S += __shfl_xor_sync(0xffffffffu, S, 1);
        }
        __syncthreads();
        if (t < NCOL && o == 0) L[c] += p * S;
        __syncthreads();
    }
    if (t < NCOL) out[(size_t)b * NCOL + col] = v;
}

extern "C" void kernel_launch(void* const* d_in, const int* in_sizes, int n_in,
                              void* d_out, int out_size) {
    const float* x = (const float*)d_in[0];
    const float* w = (const float*)d_in[1];
    if (n_in >= 2 && in_sizes[0] == NUM_C * KDIM * OUT_CH) {
        w = (const float*)d_in[0];
        x = (const float*)d_in[1];
    }
    gemm_kernel<<<dim3(KSPLIT, 2), NTHR>>>(x, w);
    routing_kernel<<<BATCH, 640>>>((float*)d_out);
    (void)out_size;
}